// round 13
// baseline (speedup 1.0000x reference)
#include <cuda_runtime.h>
#include <cstdint>

// Problem dims
#define MDIM 8192
#define NDIM 4096
#define KDIM 4096

// Tiling
#define BM 128
#define BN 128
#define BK 8
#define NKT (KDIM / BK)      // 512 k-tiles

// Identified chain hypothesis (R11 g2, corroborated by R12 correlation):
//   S = (seq ascending FMA chain over k=0..2047, from 0)
//     + (seq ascending FMA chain over k=2048..4095, from 0)
//   out = fmod(S + bias, 2)
#define TILES_PER_BLK 256    // 2048 k per half
#define NBLK 2

__device__ __forceinline__ float fmod2f(float v) {
    return fmaf(-2.0f, truncf(v * 0.5f), v);   // exact truncated fmod(v,2)
}

__global__ void __launch_bounds__(512, 1)
k_sgemm_fmod(const float* __restrict__ X, const float* __restrict__ W,
             const float* __restrict__ bias, float* __restrict__ out) {
    __shared__ float As[2][BK][BM + 4];   // [k][m]
    __shared__ float Bs[2][BK][BN + 4];   // [k][n]

    const int tid = threadIdx.x;
    const int tx = tid & 31;          // n: 32 threads x 4 cols
    const int ty = tid >> 5;          // m: 16 threads x 8 rows
    const int m0 = blockIdx.y * BM;
    const int n0 = blockIdx.x * BN;

    // loader: threads 0..255 -> A, 256..511 -> B
    const bool loadA = tid < 256;
    const int c = loadA ? tid : (tid - 256);
    const int lrow = c >> 1;
    const int lq = c & 1;
    const float* gsrc = loadA ? (X + (size_t)(m0 + lrow) * KDIM + lq * 4)
                              : (W + (size_t)(n0 + lrow) * KDIM + lq * 4);

    float S[8][4], accB[8][4];
#pragma unroll
    for (int i = 0; i < 8; i++)
#pragma unroll
        for (int j = 0; j < 4; j++) { S[i][j] = 0.0f; accB[i][j] = 0.0f; }

    // prologue: tile 0 -> buf 0
    {
        float4 v = *(const float4*)gsrc;
        float* dst = loadA ? &As[0][lq * 4][lrow] : &Bs[0][lq * 4][lrow];
        const int str = loadA ? (BM + 4) : (BN + 4);
        dst[0 * str] = v.x; dst[1 * str] = v.y; dst[2 * str] = v.z; dst[3 * str] = v.w;
    }
    __syncthreads();

    int g = 0;  // global k-tile index
#pragma unroll 1
    for (int blk = 0; blk < NBLK; blk++) {
#pragma unroll 1
        for (int t = 0; t < TILES_PER_BLK; t++, g++) {
            const int buf = g & 1;
            float4 nxt;
            const bool more = (g + 1) < NKT;
            if (more) nxt = *(const float4*)(gsrc + (size_t)(g + 1) * BK);

            // compute this k-tile: k ascending, FMA into half-chain accumulator
#pragma unroll
            for (int k = 0; k < BK; k++) {
                float4 av0 = *(const float4*)&As[buf][k][ty * 8];
                float4 av1 = *(const float4*)&As[buf][k][ty * 8 + 4];
                float4 bv  = *(const float4*)&Bs[buf][k][tx * 4];
                const float a[8] = {av0.x, av0.y, av0.z, av0.w, av1.x, av1.y, av1.z, av1.w};
                const float b[4] = {bv.x, bv.y, bv.z, bv.w};
#pragma unroll
                for (int i = 0; i < 8; i++)
#pragma unroll
                    for (int j = 0; j < 4; j++)
                        accB[i][j] = fmaf(a[i], b[j], accB[i][j]);
            }

            if (more) {
                __syncthreads();
                const int nb = buf ^ 1;
                float* dst = loadA ? &As[nb][lq * 4][lrow] : &Bs[nb][lq * 4][lrow];
                const int str = loadA ? (BM + 4) : (BN + 4);
                dst[0 * str] = nxt.x; dst[1 * str] = nxt.y;
                dst[2 * str] = nxt.z; dst[3 * str] = nxt.w;
                __syncthreads();
            }
        }
        // half boundary: one rounded add into running sum, restart half acc
#pragma unroll
        for (int i = 0; i < 8; i++)
#pragma unroll
            for (int j = 0; j < 4; j++) {
                S[i][j] = S[i][j] + accB[i][j];
                accB[i][j] = 0.0f;
            }
    }

    // epilogue: +bias (one rounding), exact truncated fmod, float4 stores
    const int col = n0 + tx * 4;
    const float4 bb = *(const float4*)(bias + col);
    const float bc[4] = {bb.x, bb.y, bb.z, bb.w};
#pragma unroll
    for (int i = 0; i < 8; i++) {
        const int row = m0 + ty * 8 + i;
        float4 v;
        v.x = fmod2f(S[i][0] + bc[0]);
        v.y = fmod2f(S[i][1] + bc[1]);
        v.z = fmod2f(S[i][2] + bc[2]);
        v.w = fmod2f(S[i][3] + bc[3]);
        *(float4*)(out + (size_t)row * NDIM + col) = v;
    }
}

extern "C" void kernel_launch(void* const* d_in, const int* in_sizes, int n_in,
                              void* d_out, int out_size) {
    const float* x = (const float*)d_in[0];
    const float* w = (const float*)d_in[1];
    const float* bias = (const float*)d_in[2];
    float* out = (float*)d_out;
    (void)in_sizes; (void)n_in; (void)out_size;

    dim3 grid(NDIM / BN, MDIM / BM);   // (32, 64)
    k_sgemm_fmod<<<grid, 512>>>(x, w, bias, out);
}

// round 14
// speedup vs baseline: 1.0270x; 1.0270x over previous
#include <cuda_runtime.h>
#include <cstdint>

// Problem dims
#define MDIM 8192
#define NDIM 4096
#define KDIM 4096

// Tiling
#define BM 128
#define BN 128
#define BK 8
#define NKT (KDIM / BK)        // 512 k-tiles
#define HALF_TILES 256         // k=2048 boundary at tile 256

// Reference chain (bitwise-locked in R13):
//   S = (asc FMA chain k=0..2047 from 0) + (asc FMA chain k=2048..4095 from 0)
//   out = fmod(S + bias, 2)   [truncated fmod, exact]
// f32x2 packing puts two DIFFERENT outputs (adjacent m) in one register pair;
// per-lane rounding of fma.rn.f32x2 / add.rn.f32x2 is identical to scalar, so
// every output's chain stays bit-identical.

// smem layout (bytes): As 2x1056 floats, Bs 2x1056 floats, spill 256x32 u64
#define ASZ 1056                       // floats per As/Bs buffer (8 * 132)
#define BS_OFFF (2 * ASZ)              // float offset of Bs
#define SPILL_OFF 16896                // byte offset of spill
#define SMEM_BYTES (SPILL_OFF + 256 * 32 * 8)   // 82432

__device__ __forceinline__ float fmod2f(float v) {
    return fmaf(-2.0f, truncf(v * 0.5f), v);   // exact truncated fmod(v,2)
}

__device__ __forceinline__ void ffma2(unsigned long long& d,
                                      unsigned long long a,
                                      unsigned long long b) {
    asm("fma.rn.f32x2 %0, %1, %2, %0;" : "+l"(d) : "l"(a), "l"(b));
}
__device__ __forceinline__ unsigned long long addf32x2(unsigned long long a,
                                                       unsigned long long b) {
    unsigned long long d;
    asm("add.rn.f32x2 %0, %1, %2;" : "=l"(d) : "l"(a), "l"(b));
    return d;
}
__device__ __forceinline__ unsigned long long dup2(float b) {
    unsigned long long d;
    asm("mov.b64 %0, {%1, %1};" : "=l"(d) : "f"(b));
    return d;
}

__global__ void __launch_bounds__(256, 2)
k_sgemm_fmod(const float* __restrict__ X, const float* __restrict__ W,
             const float* __restrict__ bias, float* __restrict__ out) {
    extern __shared__ char smem[];
    float* As = (float*)smem;                          // [2][8][132] (k-major, m rows)
    float* Bs = As + BS_OFFF;                          // [2][8][132]
    unsigned long long* spill =
        (unsigned long long*)(smem + SPILL_OFF);       // [256][32]

    const int tid = threadIdx.x;
    const int tx = tid & 15;           // n: 16 thr x 8 cols
    const int ty = tid >> 4;           // m: 16 thr x 8 rows
    const int m0 = blockIdx.y * BM;
    const int n0 = blockIdx.x * BN;

    // loader: each thread moves 1 float4 of A and 1 of B per tile
    const int lrow = tid >> 1;         // 0..127
    const int lq = tid & 1;            // which float4 of the 8-float row
    const float* ga = X + (size_t)(m0 + lrow) * KDIM + lq * 4;
    const float* gb = W + (size_t)(n0 + lrow) * KDIM + lq * 4;

    // acc pairs: 4 m-pairs x 8 n, lanes = (m even, m odd)
    unsigned long long acc[4][8];
#pragma unroll
    for (int i = 0; i < 4; i++)
#pragma unroll
        for (int j = 0; j < 8; j++) acc[i][j] = 0ull;

    // prologue: tile 0 -> buf 0
    {
        float4 va = *(const float4*)ga;
        float4 vb = *(const float4*)gb;
        float* da = As + lq * 4 * 132 + lrow;
        float* db = Bs + lq * 4 * 132 + lrow;
        da[0] = va.x; da[132] = va.y; da[264] = va.z; da[396] = va.w;
        db[0] = vb.x; db[132] = vb.y; db[264] = vb.z; db[396] = vb.w;
    }
    __syncthreads();

#pragma unroll 1
    for (int g = 0; g < NKT; g++) {
        const int buf = g & 1;
        float4 na, nb;
        const bool more = (g + 1) < NKT;
        if (more) {
            na = *(const float4*)(ga + (size_t)(g + 1) * BK);
            nb = *(const float4*)(gb + (size_t)(g + 1) * BK);
        }

        const float* ap = As + buf * ASZ + ty * 8;
        const float* bp = Bs + buf * ASZ + tx * 8;
#pragma unroll
        for (int k = 0; k < BK; k++) {
            ulonglong2 a01 = *(const ulonglong2*)(ap + k * 132);       // m pairs 0,1
            ulonglong2 a23 = *(const ulonglong2*)(ap + k * 132 + 4);   // m pairs 2,3
            float4 b0 = *(const float4*)(bp + k * 132);
            float4 b1 = *(const float4*)(bp + k * 132 + 4);
            const unsigned long long apk[4] = {a01.x, a01.y, a23.x, a23.y};
            const unsigned long long bd[8] = {
                dup2(b0.x), dup2(b0.y), dup2(b0.z), dup2(b0.w),
                dup2(b1.x), dup2(b1.y), dup2(b1.z), dup2(b1.w)};
#pragma unroll
            for (int i = 0; i < 4; i++)
#pragma unroll
                for (int j = 0; j < 8; j++)
                    ffma2(acc[i][j], apk[i], bd[j]);
        }

        // half boundary: stash t0 (k=0..2047 chains) in smem, restart acc
        if (g == HALF_TILES - 1) {
            unsigned long long* sp = spill + tid * 32;
#pragma unroll
            for (int i = 0; i < 4; i++)
#pragma unroll
                for (int j = 0; j < 8; j++) {
                    sp[i * 8 + j] = acc[i][j];
                    acc[i][j] = 0ull;
                }
        }

        __syncthreads();
        if (more) {
            const int nbuf = buf ^ 1;
            float* da = As + nbuf * ASZ + lq * 4 * 132 + lrow;
            float* db = Bs + nbuf * ASZ + lq * 4 * 132 + lrow;
            da[0] = na.x; da[132] = na.y; da[264] = na.z; da[396] = na.w;
            db[0] = nb.x; db[132] = nb.y; db[264] = nb.z; db[396] = nb.w;
        }
        __syncthreads();
    }

    // epilogue: S = t0 + t1 (per-lane add, bit-identical to scalar), +bias, fmod
    const int col = n0 + tx * 8;
    const float4 bb0 = *(const float4*)(bias + col);
    const float4 bb1 = *(const float4*)(bias + col + 4);
    const float bc[8] = {bb0.x, bb0.y, bb0.z, bb0.w, bb1.x, bb1.y, bb1.z, bb1.w};
    const unsigned long long* sp = spill + tid * 32;

#pragma unroll
    for (int i = 0; i < 4; i++) {
        unsigned long long S[8];
#pragma unroll
        for (int j = 0; j < 8; j++) S[j] = addf32x2(sp[i * 8 + j], acc[i][j]);

        const int rlo = m0 + ty * 8 + i * 2;
        float4 v0, v1;
        v0.x = fmod2f(__uint_as_float((unsigned)S[0]) + bc[0]);
        v0.y = fmod2f(__uint_as_float((unsigned)S[1]) + bc[1]);
        v0.z = fmod2f(__uint_as_float((unsigned)S[2]) + bc[2]);
        v0.w = fmod2f(__uint_as_float((unsigned)S[3]) + bc[3]);
        v1.x = fmod2f(__uint_as_float((unsigned)S[4]) + bc[4]);
        v1.y = fmod2f(__uint_as_float((unsigned)S[5]) + bc[5]);
        v1.z = fmod2f(__uint_as_float((unsigned)S[6]) + bc[6]);
        v1.w = fmod2f(__uint_as_float((unsigned)S[7]) + bc[7]);
        *(float4*)(out + (size_t)rlo * NDIM + col) = v0;
        *(float4*)(out + (size_t)rlo * NDIM + col + 4) = v1;

        float4 u0, u1;
        u0.x = fmod2f(__uint_as_float((unsigned)(S[0] >> 32)) + bc[0]);
        u0.y = fmod2f(__uint_as_float((unsigned)(S[1] >> 32)) + bc[1]);
        u0.z = fmod2f(__uint_as_float((unsigned)(S[2] >> 32)) + bc[2]);
        u0.w = fmod2f(__uint_as_float((unsigned)(S[3] >> 32)) + bc[3]);
        u1.x = fmod2f(__uint_as_float((unsigned)(S[4] >> 32)) + bc[4]);
        u1.y = fmod2f(__uint_as_float((unsigned)(S[5] >> 32)) + bc[5]);
        u1.z = fmod2f(__uint_as_float((unsigned)(S[6] >> 32)) + bc[6]);
        u1.w = fmod2f(__uint_as_float((unsigned)(S[7] >> 32)) + bc[7]);
        *(float4*)(out + (size_t)(rlo + 1) * NDIM + col) = u0;
        *(float4*)(out + (size_t)(rlo + 1) * NDIM + col + 4) = u1;
    }
}

extern "C" void kernel_launch(void* const* d_in, const int* in_sizes, int n_in,
                              void* d_out, int out_size) {
    const float* x = (const float*)d_in[0];
    const float* w = (const float*)d_in[1];
    const float* bias = (const float*)d_in[2];
    float* out = (float*)d_out;
    (void)in_sizes; (void)n_in; (void)out_size;

    static int attr_set = 0;
    if (!attr_set) {
        cudaFuncSetAttribute(k_sgemm_fmod,
                             cudaFuncAttributeMaxDynamicSharedMemorySize, SMEM_BYTES);
        attr_set = 1;
    }
    dim3 grid(NDIM / BN, MDIM / BM);   // (32, 64)
    k_sgemm_fmod<<<grid, 256, SMEM_BYTES>>>(x, w, bias, out);
}

// round 15
// speedup vs baseline: 1.2028x; 1.1711x over previous
#include <cuda_runtime.h>
#include <cstdint>

// Problem dims
#define MDIM 8192
#define NDIM 4096
#define KDIM 4096

// Tiling: CTA 256x128, thread tile 16x8 (as 8 m-pairs x 8 n), 256 threads
#define BM 256
#define BN 128
#define BK 8
#define NKT (KDIM / BK)        // 512
#define HALF_TILES 256         // k=2048 boundary

// smem: As[2][8][260] floats, Bs[2][8][132] floats, spill[256][64] u64
#define AROW 260
#define BROW 132
#define ABUF (BK * AROW)              // 2080 floats
#define BBUF (BK * BROW)              // 1056 floats
#define BS_OFFF (2 * ABUF)            // float offset of Bs
#define SPILL_OFF ((2 * ABUF + 2 * BBUF) * 4)   // 25088 bytes
#define SMEM_BYTES (SPILL_OFF + 256 * 64 * 8)   // 156160

// Reference chain (bitwise-locked): per output two ascending FMA chains over
// k-halves of 2048 (each from 0), merged with one add, +bias, truncated fmod.
// f32x2 lanes hold two DIFFERENT outputs (adjacent m) -> per-output chain
// identical to scalar.

__device__ __forceinline__ float fmod2f(float v) {
    return fmaf(-2.0f, truncf(v * 0.5f), v);
}
__device__ __forceinline__ void ffma2(unsigned long long& d,
                                      unsigned long long a,
                                      unsigned long long b) {
    asm("fma.rn.f32x2 %0, %1, %2, %0;" : "+l"(d) : "l"(a), "l"(b));
}
__device__ __forceinline__ unsigned long long addf32x2(unsigned long long a,
                                                       unsigned long long b) {
    unsigned long long d;
    asm("add.rn.f32x2 %0, %1, %2;" : "=l"(d) : "l"(a), "l"(b));
    return d;
}
__device__ __forceinline__ unsigned long long dup2(float b) {
    unsigned long long d;
    asm("mov.b64 %0, {%1, %1};" : "=l"(d) : "f"(b));
    return d;
}

__global__ void __launch_bounds__(256, 1)
k_sgemm_fmod(const float* __restrict__ X, const float* __restrict__ W,
             const float* __restrict__ bias, float* __restrict__ out) {
    extern __shared__ char smem[];
    float* As = (float*)smem;                      // [2][8][260]
    float* Bs = As + BS_OFFF;                      // [2][8][132]
    unsigned long long* spill =
        (unsigned long long*)(smem + SPILL_OFF);   // [256][64]

    const int tid = threadIdx.x;
    const int tx = tid & 15;          // n: 16 thr x 8 cols
    const int ty = tid >> 4;          // m: 16 thr x 16 rows
    const int m0 = blockIdx.y * BM;
    const int n0 = blockIdx.x * BN;

    // loaders: A = 512 float4 chunks (2/thread), B = 256 chunks (1/thread)
    const int ar0 = tid >> 1, aq0 = tid & 1;            // chunk tid
    const int ar1 = (tid + 256) >> 1, aq1 = aq0;        // chunk tid+256
    const int br = tid >> 1, bq = tid & 1;
    const float* ga0 = X + (size_t)(m0 + ar0) * KDIM + aq0 * 4;
    const float* ga1 = X + (size_t)(m0 + ar1) * KDIM + aq1 * 4;
    const float* gb  = W + (size_t)(n0 + br) * KDIM + bq * 4;

    unsigned long long acc[8][8];   // 8 m-pairs x 8 n
#pragma unroll
    for (int i = 0; i < 8; i++)
#pragma unroll
        for (int j = 0; j < 8; j++) acc[i][j] = 0ull;

    // prologue: tile 0 -> buf 0
    {
        float4 a0 = *(const float4*)ga0;
        float4 a1 = *(const float4*)ga1;
        float4 b0 = *(const float4*)gb;
        float* d0 = As + aq0 * 4 * AROW + ar0;
        float* d1 = As + aq1 * 4 * AROW + ar1;
        float* d2 = Bs + bq * 4 * BROW + br;
        d0[0] = a0.x; d0[AROW] = a0.y; d0[2 * AROW] = a0.z; d0[3 * AROW] = a0.w;
        d1[0] = a1.x; d1[AROW] = a1.y; d1[2 * AROW] = a1.z; d1[3 * AROW] = a1.w;
        d2[0] = b0.x; d2[BROW] = b0.y; d2[2 * BROW] = b0.z; d2[3 * BROW] = b0.w;
    }
    __syncthreads();

#pragma unroll 1
    for (int g = 0; g < NKT; g++) {
        const int buf = g & 1;
        float4 na0, na1, nb0;
        const bool more = (g + 1) < NKT;
        if (more) {
            const size_t ko = (size_t)(g + 1) * BK;
            na0 = *(const float4*)(ga0 + ko);
            na1 = *(const float4*)(ga1 + ko);
            nb0 = *(const float4*)(gb + ko);
        }

        const float* ap = As + buf * ABUF + ty * 16;
        const float* bp = Bs + buf * BBUF + tx * 8;
#pragma unroll
        for (int k = 0; k < BK; k++) {
            ulonglong2 aA = *(const ulonglong2*)(ap + k * AROW);
            ulonglong2 aB = *(const ulonglong2*)(ap + k * AROW + 4);
            ulonglong2 aC = *(const ulonglong2*)(ap + k * AROW + 8);
            ulonglong2 aD = *(const ulonglong2*)(ap + k * AROW + 12);
            float4 b0 = *(const float4*)(bp + k * BROW);
            float4 b1 = *(const float4*)(bp + k * BROW + 4);
            const unsigned long long apk[8] = {aA.x, aA.y, aB.x, aB.y,
                                               aC.x, aC.y, aD.x, aD.y};
            const unsigned long long bd[8] = {
                dup2(b0.x), dup2(b0.y), dup2(b0.z), dup2(b0.w),
                dup2(b1.x), dup2(b1.y), dup2(b1.z), dup2(b1.w)};
#pragma unroll
            for (int i = 0; i < 8; i++)
#pragma unroll
                for (int j = 0; j < 8; j++)
                    ffma2(acc[i][j], apk[i], bd[j]);
        }

        // k=2048 boundary: stash first-half chains, restart accumulators
        if (g == HALF_TILES - 1) {
            unsigned long long* sp = spill + tid * 64;
#pragma unroll
            for (int i = 0; i < 8; i++)
#pragma unroll
                for (int j = 0; j < 8; j++) {
                    sp[i * 8 + j] = acc[i][j];
                    acc[i][j] = 0ull;
                }
        }

        __syncthreads();
        if (more) {
            const int nbuf = buf ^ 1;
            float* d0 = As + nbuf * ABUF + aq0 * 4 * AROW + ar0;
            float* d1 = As + nbuf * ABUF + aq1 * 4 * AROW + ar1;
            float* d2 = Bs + nbuf * BBUF + bq * 4 * BROW + br;
            d0[0] = na0.x; d0[AROW] = na0.y; d0[2 * AROW] = na0.z; d0[3 * AROW] = na0.w;
            d1[0] = na1.x; d1[AROW] = na1.y; d1[2 * AROW] = na1.z; d1[3 * AROW] = na1.w;
            d2[0] = nb0.x; d2[BROW] = nb0.y; d2[2 * BROW] = nb0.z; d2[3 * BROW] = nb0.w;
        }
        __syncthreads();
    }

    // epilogue: S = t0 + t1 (per-lane), +bias, exact fmod
    const int col = n0 + tx * 8;
    const float4 bb0 = *(const float4*)(bias + col);
    const float4 bb1 = *(const float4*)(bias + col + 4);
    const float bc[8] = {bb0.x, bb0.y, bb0.z, bb0.w, bb1.x, bb1.y, bb1.z, bb1.w};
    const unsigned long long* sp = spill + tid * 64;

#pragma unroll
    for (int i = 0; i < 8; i++) {
        unsigned long long S[8];
#pragma unroll
        for (int j = 0; j < 8; j++) S[j] = addf32x2(sp[i * 8 + j], acc[i][j]);

        const int rlo = m0 + ty * 16 + i * 2;
        float4 v0, v1, u0, u1;
        v0.x = fmod2f(__uint_as_float((unsigned)S[0]) + bc[0]);
        v0.y = fmod2f(__uint_as_float((unsigned)S[1]) + bc[1]);
        v0.z = fmod2f(__uint_as_float((unsigned)S[2]) + bc[2]);
        v0.w = fmod2f(__uint_as_float((unsigned)S[3]) + bc[3]);
        v1.x = fmod2f(__uint_as_float((unsigned)S[4]) + bc[4]);
        v1.y = fmod2f(__uint_as_float((unsigned)S[5]) + bc[5]);
        v1.z = fmod2f(__uint_as_float((unsigned)S[6]) + bc[6]);
        v1.w = fmod2f(__uint_as_float((unsigned)S[7]) + bc[7]);
        u0.x = fmod2f(__uint_as_float((unsigned)(S[0] >> 32)) + bc[0]);
        u0.y = fmod2f(__uint_as_float((unsigned)(S[1] >> 32)) + bc[1]);
        u0.z = fmod2f(__uint_as_float((unsigned)(S[2] >> 32)) + bc[2]);
        u0.w = fmod2f(__uint_as_float((unsigned)(S[3] >> 32)) + bc[3]);
        u1.x = fmod2f(__uint_as_float((unsigned)(S[4] >> 32)) + bc[4]);
        u1.y = fmod2f(__uint_as_float((unsigned)(S[5] >> 32)) + bc[5]);
        u1.z = fmod2f(__uint_as_float((unsigned)(S[6] >> 32)) + bc[6]);
        u1.w = fmod2f(__uint_as_float((unsigned)(S[7] >> 32)) + bc[7]);
        *(float4*)(out + (size_t)rlo * NDIM + col) = v0;
        *(float4*)(out + (size_t)rlo * NDIM + col + 4) = v1;
        *(float4*)(out + (size_t)(rlo + 1) * NDIM + col) = u0;
        *(float4*)(out + (size_t)(rlo + 1) * NDIM + col + 4) = u1;
    }
}

extern "C" void kernel_launch(void* const* d_in, const int* in_sizes, int n_in,
                              void* d_out, int out_size) {
    const float* x = (const float*)d_in[0];
    const float* w = (const float*)d_in[1];
    const float* bias = (const float*)d_in[2];
    float* out = (float*)d_out;
    (void)in_sizes; (void)n_in; (void)out_size;

    static int attr_set = 0;
    if (!attr_set) {
        cudaFuncSetAttribute(k_sgemm_fmod,
                             cudaFuncAttributeMaxDynamicSharedMemorySize, SMEM_BYTES);
        attr_set = 1;
    }
    dim3 grid(NDIM / BN, MDIM / BM);   // (32, 32)
    k_sgemm_fmod<<<grid, 256, SMEM_BYTES>>>(x, w, bias, out);
}